// round 7
// baseline (speedup 1.0000x reference)
#include <cuda_runtime.h>
#include <cstdint>

#define B 8
#define C 128
#define H 256
#define W 256
#define HW (H*W)        // 65536
#define HW4 (HW/4)      // 16384

// per-batch warp-unit counts
#define POOL_U 512      // warp = 32 consecutive float4-pixels, all 128 channels
#define CONV_U 512      // warp = 128 consecutive pixels (4 per lane)
#define MUL_U  4096     // warp = 32 float4-pixels x 16 channels
#define STEP_T (CONV_U + MUL_U + POOL_U)                 // 5120
#define TOTAL_T (POOL_U + 7 * STEP_T + CONV_U + MUL_U)   // 40960

__device__ float g_pooled[B * HW];
__device__ float g_attn[B * HW];
__device__ int   g_ticket;
__device__ int   g_pool_done[B];
__device__ int   g_conv_done[B];

__global__ void reset_kernel() {
    g_ticket = 0;
    #pragma unroll
    for (int i = 0; i < B; ++i) { g_pool_done[i] = 0; g_conv_done[i] = 0; }
}

// ---------------------------------------------------------------------------
// Persistent pipeline, WARP-granular units, no block barriers, no smem.
// Ticket order (dependency order -> deadlock-free pull model):
//   [pool(0) x512]
//   step s=1..7: [conv(s-1) x512][ (8 x mul(s-1), 1 x pool(s)) x512 ]
//   tail:        [conv(7) x512][ mul(7) x4096 ]
// ---------------------------------------------------------------------------
__global__ void __launch_bounds__(256, 6) pipeline_kernel(
        const float* __restrict__ x, float* __restrict__ out,
        const float* __restrict__ cw, const float* __restrict__ cb)
{
    const int lane = threadIdx.x & 31;

    for (;;) {
        int t;
        if (lane == 0) t = atomicAdd(&g_ticket, 1);
        t = __shfl_sync(0xffffffffu, t, 0);
        if (t >= TOTAL_T) break;

        int role, b, u;           // 0=pool 1=conv 2=mul
        if (t < POOL_U) {
            role = 0; b = 0; u = t;
        } else if (t < POOL_U + 7 * STEP_T) {
            int r  = t - POOL_U;
            int st = r / STEP_T;
            int l  = r - st * STEP_T;
            if (l < CONV_U) { role = 1; b = st; u = l; }
            else {
                int l2 = l - CONV_U;
                int q  = l2 / 9;
                int m  = l2 - q * 9;
                if (m < 8) { role = 2; b = st;     u = q * 8 + m; }
                else       { role = 0; b = st + 1; u = q; }
            }
        } else {
            int l = t - (POOL_U + 7 * STEP_T);
            if (l < CONV_U) { role = 1; b = 7; u = l; }
            else            { role = 2; b = 7; u = l - CONV_U; }
        }

        if (role == 0) {
            // ---- pool: lane = one float4 pixel, reduce over 128 channels ----
            const int hw4 = u * 32 + lane;
            const float4* p = reinterpret_cast<const float4*>(x)
                              + (size_t)b * C * HW4 + hw4;
            float4 m4 = make_float4(-3.4e38f, -3.4e38f, -3.4e38f, -3.4e38f);
            #pragma unroll 4
            for (int c = 0; c < C; c += 4) {
                float4 v0 = p[(size_t)(c + 0) * HW4];
                float4 v1 = p[(size_t)(c + 1) * HW4];
                float4 v2 = p[(size_t)(c + 2) * HW4];
                float4 v3 = p[(size_t)(c + 3) * HW4];
                m4.x = fmaxf(fmaxf(m4.x, v0.x), fmaxf(v1.x, fmaxf(v2.x, v3.x)));
                m4.y = fmaxf(fmaxf(m4.y, v0.y), fmaxf(v1.y, fmaxf(v2.y, v3.y)));
                m4.z = fmaxf(fmaxf(m4.z, v0.z), fmaxf(v1.z, fmaxf(v2.z, v3.z)));
                m4.w = fmaxf(fmaxf(m4.w, v0.w), fmaxf(v1.w, fmaxf(v2.w, v3.w)));
            }
            reinterpret_cast<float4*>(g_pooled)[(size_t)b * HW4 + hw4] = m4;
            __threadfence();
            __syncwarp();
            if (lane == 0) atomicAdd(&g_pool_done[b], 1);
        } else if (role == 1) {
            // ---- conv+sigmoid: 128 consecutive px in a row, 4 per lane ----
            const int row = u >> 1;
            const int x0  = (u & 1) * 128 + lane * 4;

            if (lane == 0) {
                while (*(volatile int*)&g_pool_done[b] < POOL_U) __nanosleep(64);
            }
            __syncwarp();
            __threadfence();

            const float* pb = g_pooled + b * HW;
            const float bias = __ldg(&cb[0]);
            float a0 = bias, a1 = bias, a2 = bias, a3 = bias;
            #pragma unroll
            for (int i = 0; i < 7; ++i) {
                const int gy = row + i - 3;
                const bool rv = (gy >= 0) && (gy < H);
                float r[13];
                #pragma unroll
                for (int k2 = 0; k2 < 13; ++k2) {
                    int gx = x0 + k2 - 3;
                    r[k2] = (rv && gx >= 0 && gx < W) ? __ldg(&pb[gy * W + gx]) : 0.0f;
                }
                #pragma unroll
                for (int k = 0; k < 7; ++k) {
                    float w = __ldg(&cw[i * 7 + k]);
                    a0 = fmaf(r[k + 0], w, a0);
                    a1 = fmaf(r[k + 1], w, a1);
                    a2 = fmaf(r[k + 2], w, a2);
                    a3 = fmaf(r[k + 3], w, a3);
                }
            }
            float4 s4;
            s4.x = 1.0f / (1.0f + __expf(-a0));
            s4.y = 1.0f / (1.0f + __expf(-a1));
            s4.z = 1.0f / (1.0f + __expf(-a2));
            s4.w = 1.0f / (1.0f + __expf(-a3));
            reinterpret_cast<float4*>(g_attn)[((size_t)b * HW + row * W + x0) >> 2] = s4;
            __threadfence();
            __syncwarp();
            if (lane == 0) atomicAdd(&g_conv_done[b], 1);
        } else {
            // ---- mul: lane = one float4 pixel, 16 channels ----
            const int chg = u & 7;
            const int sp  = u >> 3;
            const int hw4 = sp * 32 + lane;

            if (lane == 0) {
                while (*(volatile int*)&g_conv_done[b] < CONV_U) __nanosleep(64);
            }
            __syncwarp();
            __threadfence();

            const float4 a = __ldg(reinterpret_cast<const float4*>(g_attn)
                                   + (size_t)b * HW4 + hw4);
            const float4* xp = reinterpret_cast<const float4*>(x)
                               + ((size_t)b * C + chg * 16) * HW4 + hw4;
            float4* op = reinterpret_cast<float4*>(out)
                         + ((size_t)b * C + chg * 16) * HW4 + hw4;
            #pragma unroll
            for (int h = 0; h < 4; ++h) {
                float4 v0 = __ldcs(xp + (size_t)(h * 4 + 0) * HW4);
                float4 v1 = __ldcs(xp + (size_t)(h * 4 + 1) * HW4);
                float4 v2 = __ldcs(xp + (size_t)(h * 4 + 2) * HW4);
                float4 v3 = __ldcs(xp + (size_t)(h * 4 + 3) * HW4);
                v0.x *= a.x; v0.y *= a.y; v0.z *= a.z; v0.w *= a.w;
                v1.x *= a.x; v1.y *= a.y; v1.z *= a.z; v1.w *= a.w;
                v2.x *= a.x; v2.y *= a.y; v2.z *= a.z; v2.w *= a.w;
                v3.x *= a.x; v3.y *= a.y; v3.z *= a.z; v3.w *= a.w;
                __stcs(op + (size_t)(h * 4 + 0) * HW4, v0);
                __stcs(op + (size_t)(h * 4 + 1) * HW4, v1);
                __stcs(op + (size_t)(h * 4 + 2) * HW4, v2);
                __stcs(op + (size_t)(h * 4 + 3) * HW4, v3);
            }
        }
    }
}

// ---------------------------------------------------------------------------
extern "C" void kernel_launch(void* const* d_in, const int* in_sizes, int n_in,
                              void* d_out, int out_size) {
    const float* x  = (const float*)d_in[0];
    const float* cw = (const float*)d_in[1];
    const float* cb = (const float*)d_in[2];
    float* out = (float*)d_out;

    reset_kernel<<<1, 1>>>();
    pipeline_kernel<<<888, 256>>>(x, out, cw, cb);   // 148 SMs x 6 blocks
}

// round 8
// speedup vs baseline: 2.3007x; 2.3007x over previous
#include <cuda_runtime.h>
#include <cstdint>

#define B 8
#define C 128
#define H 256
#define W 256
#define HW (H*W)        // 65536
#define HW4 (HW/4)      // 16384

__device__ float g_pooled[B * HW];

// ---------------------------------------------------------------------------
// poolPair: batches b0, b0+1. grid 512 x 256 threads.
// Block: (batch, 64 float4-pixels); threads split 4 ways over channels (32 ea).
// Plain loads -> x stays L2-resident for the convMul launch that follows.
// ---------------------------------------------------------------------------
__global__ void __launch_bounds__(256) pool_pair_kernel(
        const float* __restrict__ x, int b0)
{
    __shared__ float4 red[256];
    const int rid   = blockIdx.x;
    const int b     = b0 + (rid >> 8);
    const int inner = rid & 255;
    const int tid = threadIdx.x;
    const int grp = tid >> 6;          // 0..3  (32 channels each)
    const int pix = tid & 63;
    const int hw4 = inner * 64 + pix;

    const float4* p = reinterpret_cast<const float4*>(x)
                      + ((size_t)b * C + (size_t)grp * 32) * HW4 + hw4;
    float4 m = p[0];
    #pragma unroll 8
    for (int c = 1; c < 32; ++c) {
        float4 v = p[(size_t)c * HW4];
        m.x = fmaxf(m.x, v.x);
        m.y = fmaxf(m.y, v.y);
        m.z = fmaxf(m.z, v.z);
        m.w = fmaxf(m.w, v.w);
    }
    red[tid] = m;
    __syncthreads();

    if (grp == 0) {
        float4 a  = red[pix];
        float4 b1 = red[64 + pix];
        float4 c1 = red[128 + pix];
        float4 d1 = red[192 + pix];
        a.x = fmaxf(fmaxf(a.x, b1.x), fmaxf(c1.x, d1.x));
        a.y = fmaxf(fmaxf(a.y, b1.y), fmaxf(c1.y, d1.y));
        a.z = fmaxf(fmaxf(a.z, b1.z), fmaxf(c1.z, d1.z));
        a.w = fmaxf(fmaxf(a.w, b1.w), fmaxf(c1.w, d1.w));
        reinterpret_cast<float4*>(g_pooled)[(size_t)b * HW4 + hw4] = a;
    }
}

// ---------------------------------------------------------------------------
// convMulPair: batches b0, b0+1. grid 1024 x 256 threads.
// Block = (batch, spatial tile 64x16, channel group of 16).
// Loads pooled halo (L2), computes 7x7 conv + sigmoid in-register (redundant
// across the 8 channel groups - trivial FLOPs), then streams 16 channels:
//   out = x * attn   with __ldcs (x dead after) / __stcs (don't evict x).
// ---------------------------------------------------------------------------
__global__ void __launch_bounds__(256) convmul_pair_kernel(
        const float* __restrict__ x, float* __restrict__ out,
        const float* __restrict__ cw, const float* __restrict__ cb, int b0)
{
    __shared__ float s[22][72];        // 70 cols used
    const int rid = blockIdx.x;
    const int b   = b0 + (rid >> 9);
    const int u   = rid & 511;
    const int tile = u >> 3;           // 0..63
    const int chg  = u & 7;            // 0..7 (16 channels)
    const int tx0  = (tile & 3) * 64;
    const int ty0  = (tile >> 2) * 16;
    const int tid  = threadIdx.x;

    const float* pb = g_pooled + b * HW;
    for (int i = tid; i < 22 * 70; i += 256) {
        int ly = i / 70;
        int lx = i - ly * 70;
        int gy = ty0 + ly - 3;
        int gx = tx0 + lx - 3;
        float v = 0.0f;
        if (gy >= 0 && gy < H && gx >= 0 && gx < W) v = pb[gy * W + gx];
        s[ly][lx] = v;
    }
    __syncthreads();

    float wr[49];
    #pragma unroll
    for (int i = 0; i < 49; ++i) wr[i] = __ldg(&cw[i]);
    const float bias = __ldg(&cb[0]);

    const int lx4 = tid & 15;          // float4 column within tile
    const int ly  = tid >> 4;          // row 0..15

    float a4[4];
    #pragma unroll
    for (int j = 0; j < 4; ++j) {
        float acc = bias;
        #pragma unroll
        for (int i = 0; i < 7; ++i)
            #pragma unroll
            for (int k = 0; k < 7; ++k)
                acc = fmaf(s[ly + i][lx4 * 4 + j + k], wr[i * 7 + k], acc);
        a4[j] = 1.0f / (1.0f + __expf(-acc));
    }

    const int hw4 = (ty0 + ly) * (W / 4) + (tx0 >> 2) + lx4;
    const float4* xp = reinterpret_cast<const float4*>(x)
                       + ((size_t)b * C + chg * 16) * HW4 + hw4;
    float4* op = reinterpret_cast<float4*>(out)
                 + ((size_t)b * C + chg * 16) * HW4 + hw4;

    #pragma unroll
    for (int h = 0; h < 2; ++h) {
        float4 v[8];
        #pragma unroll
        for (int j = 0; j < 8; ++j)
            v[j] = __ldcs(xp + (size_t)(h * 8 + j) * HW4);
        #pragma unroll
        for (int j = 0; j < 8; ++j) {
            v[j].x *= a4[0]; v[j].y *= a4[1]; v[j].z *= a4[2]; v[j].w *= a4[3];
            __stcs(op + (size_t)(h * 8 + j) * HW4, v[j]);
        }
    }
}

// ---------------------------------------------------------------------------
extern "C" void kernel_launch(void* const* d_in, const int* in_sizes, int n_in,
                              void* d_out, int out_size) {
    const float* x  = (const float*)d_in[0];
    const float* cw = (const float*)d_in[1];
    const float* cb = (const float*)d_in[2];
    float* out = (float*)d_out;

    for (int p = 0; p < 4; ++p) {
        pool_pair_kernel<<<512, 256>>>(x, 2 * p);
        convmul_pair_kernel<<<1024, 256>>>(x, out, cw, cb, 2 * p);
    }
}

// round 10
// speedup vs baseline: 2.7123x; 1.1789x over previous
#include <cuda_runtime.h>
#include <cstdint>

#define B 8
#define C 128
#define H 256
#define W 256
#define HW (H*W)        // 65536
#define HW4 (HW/4)      // 16384

__device__ float g_pooled[B * HW];
__device__ float g_attn[B * HW];

// ---------------------------------------------------------------------------
// poolPair: batches b0, b0+1. grid 512, block 256.
// Block = (batch, 64 float4-pixels); 4-way channel split, smem reduce.
// Plain loads -> leaves x_pair L2-resident for the mulPair launch.
// ---------------------------------------------------------------------------
__global__ void __launch_bounds__(256) pool_pair_kernel(
        const float* __restrict__ x, int b0)
{
    __shared__ float4 red[256];
    const int rid   = blockIdx.x;
    const int b     = b0 + (rid >> 8);
    const int inner = rid & 255;
    const int tid = threadIdx.x;
    const int grp = tid >> 6;
    const int pix = tid & 63;
    const int hw4 = inner * 64 + pix;

    const float4* p = reinterpret_cast<const float4*>(x)
                      + ((size_t)b * C + (size_t)grp * 32) * HW4 + hw4;
    float4 m = p[0];
    #pragma unroll 8
    for (int c = 1; c < 32; ++c) {
        float4 v = p[(size_t)c * HW4];
        m.x = fmaxf(m.x, v.x);
        m.y = fmaxf(m.y, v.y);
        m.z = fmaxf(m.z, v.z);
        m.w = fmaxf(m.w, v.w);
    }
    red[tid] = m;
    __syncthreads();

    if (grp == 0) {
        float4 a  = red[pix];
        float4 b1 = red[64 + pix];
        float4 c1 = red[128 + pix];
        float4 d1 = red[192 + pix];
        a.x = fmaxf(fmaxf(a.x, b1.x), fmaxf(c1.x, d1.x));
        a.y = fmaxf(fmaxf(a.y, b1.y), fmaxf(c1.y, d1.y));
        a.z = fmaxf(fmaxf(a.z, b1.z), fmaxf(c1.z, d1.z));
        a.w = fmaxf(fmaxf(a.w, b1.w), fmaxf(c1.w, d1.w));
        reinterpret_cast<float4*>(g_pooled)[(size_t)b * HW4 + hw4] = a;
    }
}

// ---------------------------------------------------------------------------
// convPair: batches b0, b0+1. grid (4,16,2), block 256. Smem-tile 7x7 conv
// + sigmoid -> g_attn. Tiny (~0.5MB in / 0.5MB out per batch).
// ---------------------------------------------------------------------------
#define TW 64
#define TH 16

__global__ void __launch_bounds__(256) conv_pair_kernel(
        const float* __restrict__ cw, const float* __restrict__ cb, int b0)
{
    __shared__ float s[TH + 6][TW + 8];
    const int b   = b0 + blockIdx.z;
    const int tx0 = blockIdx.x * TW;
    const int ty0 = blockIdx.y * TH;
    const float* pb = g_pooled + b * HW;

    for (int i = threadIdx.x; i < (TH + 6) * (TW + 6); i += 256) {
        int ly = i / (TW + 6);
        int lx = i - ly * (TW + 6);
        int gy = ty0 + ly - 3;
        int gx = tx0 + lx - 3;
        float v = 0.0f;
        if (gy >= 0 && gy < H && gx >= 0 && gx < W) v = pb[gy * W + gx];
        s[ly][lx] = v;
    }
    __syncthreads();

    float wr[49];
    #pragma unroll
    for (int i = 0; i < 49; ++i) wr[i] = __ldg(&cw[i]);
    const float bias = __ldg(&cb[0]);

    const int lx  = threadIdx.x & (TW - 1);
    const int ly0 = threadIdx.x >> 6;        // 0..3

    #pragma unroll
    for (int r = 0; r < TH; r += 4) {
        const int ly = ly0 + r;
        float acc = bias;
        #pragma unroll
        for (int i = 0; i < 7; ++i)
            #pragma unroll
            for (int j = 0; j < 7; ++j)
                acc = fmaf(s[ly + i][lx + j], wr[i * 7 + j], acc);
        float sg = 1.0f / (1.0f + __expf(-acc));
        g_attn[b * HW + (ty0 + ly) * W + tx0 + lx] = sg;
    }
}

// ---------------------------------------------------------------------------
// mulPair: batches b0, b0+1. grid 16384, block 256, ONE float4 per thread
// (R1's proven 6.1 TB/s shape, ~20 regs). x reads via __ldcs should hit L2
// (left there by poolPair); out writes via __stcs (streaming, protect x).
// attn (1MB/pair) is L2-resident, 128x reuse.
// ---------------------------------------------------------------------------
__global__ void __launch_bounds__(256) mul_pair_kernel(
        const float* __restrict__ x, float* __restrict__ out, int b0)
{
    size_t i = (size_t)blockIdx.x * blockDim.x + threadIdx.x;  // float4 idx in pair
    int hw4 = (int)(i & (HW4 - 1));
    int bi  = (int)(i >> 21);                  // 0 or 1 (i / (C*HW4))
    size_t gi = ((size_t)(b0 + bi)) * C * HW4 + (i & ((1u << 21) - 1));

    float4 a = __ldg(reinterpret_cast<const float4*>(g_attn)
                     + (size_t)(b0 + bi) * HW4 + hw4);
    float4 v = __ldcs(reinterpret_cast<const float4*>(x) + gi);
    v.x *= a.x; v.y *= a.y; v.z *= a.z; v.w *= a.w;
    __stcs(reinterpret_cast<float4*>(out) + gi, v);
}

// ---------------------------------------------------------------------------
extern "C" void kernel_launch(void* const* d_in, const int* in_sizes, int n_in,
                              void* d_out, int out_size) {
    const float* x  = (const float*)d_in[0];
    const float* cw = (const float*)d_in[1];
    const float* cb = (const float*)d_in[2];
    float* out = (float*)d_out;

    dim3 gc(W / TW, H / TH, 2);
    for (int p = 0; p < 4; ++p) {
        const int b0 = 2 * p;
        pool_pair_kernel<<<512, 256>>>(x, b0);
        conv_pair_kernel<<<gc, 256>>>(cw, cb, b0);
        mul_pair_kernel<<<2 * C * HW4 / 256, 256>>>(x, out, b0);
    }
}